// round 5
// baseline (speedup 1.0000x reference)
#include <cuda_runtime.h>
#include <cuda_bf16.h>
#include <cstdint>

// MaxUnpooling2DMod: out[b, y(idx), x(idx), c] += in[b,h,w,c]
//   in  [8,128,128,64] -> 2^23 floats, out [8,256,256,64] -> 2^25 floats
// decode: out_off = (b << 22) + (idx & ~63) + (lin & 63)
//
// PDL chain with EARLY release: kernel b
//   loads batch b -> zeros slab b+1 -> launch_dependents -> wait -> atomics(slab b)
// Zeroing slab b+1 depends on nothing (untouched range), so the dependent is
// released after the short zero phase; atomic drains of consecutive kernels
// overlap on freed SM slots. Zeros precede the trigger => visible to the
// dependent after its wait (contract validated in R4).

static constexpr int BLOCK     = 256;
static constexpr int GRID      = 512;
static constexpr int THREADS   = GRID * BLOCK;            // 131072
static constexpr int SLAB_F4   = (1 << 22) / 4;           // 1,048,576 float4/slab
static constexpr int ZERO_PER_T = SLAB_F4 / THREADS;      // 8
static constexpr int ELEMS_PER_T = (1 << 20) / THREADS;   // 8 (two quads)

__global__ void __launch_bounds__(BLOCK)
unpool_pdl2_kernel(const float* __restrict__ in,
                   const int*   __restrict__ idx,
                   float*       __restrict__ out,
                   int bs,     // batch to scatter (-1 = none)
                   int bz)     // slab to zero    (-1 = none)
{
    const int t = blockIdx.x * BLOCK + threadIdx.x;

    // ---- streaming loads (independent of everything) ----
    float4 v0, v1;
    int4   id0, id1;
    int    e0 = 0;
    if (bs >= 0) {
        e0 = (bs << 20) + t * ELEMS_PER_T;
        const float4* in4  = reinterpret_cast<const float4*>(in)  + (e0 >> 2);
        const int4*   idx4 = reinterpret_cast<const int4*>(idx)   + (e0 >> 2);
        v0  = __ldcs(in4 + 0);   v1  = __ldcs(in4 + 1);
        id0 = __ldcs(idx4 + 0);  id1 = __ldcs(idx4 + 1);
    }

    // ---- zero slab bz (untouched by any active kernel; no wait needed) ----
    if (bz >= 0) {
        float4* o4 = reinterpret_cast<float4*>(out) + (size_t)bz * SLAB_F4;
        const float4 z = make_float4(0.f, 0.f, 0.f, 0.f);
        #pragma unroll
        for (int j = 0; j < ZERO_PER_T; j++)
            o4[t + j * THREADS] = z;
    }

    // ---- release dependent: its slab (bz) is zeroed ----
    asm volatile("griddepcontrol.launch_dependents;" ::: "memory");

    // ---- wait for OUR slab's zeros (from predecessor), then scatter ----
    asm volatile("griddepcontrol.wait;" ::: "memory");

    if (bs >= 0) {
        const int base = bs << 22;
        const int c0   = e0 & 63;              // e0 is a multiple of 8
        atomicAdd(out + base + (id0.x & ~63) + (c0 + 0), v0.x);
        atomicAdd(out + base + (id0.y & ~63) + (c0 + 1), v0.y);
        atomicAdd(out + base + (id0.z & ~63) + (c0 + 2), v0.z);
        atomicAdd(out + base + (id0.w & ~63) + (c0 + 3), v0.w);
        atomicAdd(out + base + (id1.x & ~63) + (c0 + 4), v1.x);
        atomicAdd(out + base + (id1.y & ~63) + (c0 + 5), v1.y);
        atomicAdd(out + base + (id1.z & ~63) + (c0 + 6), v1.z);
        atomicAdd(out + base + (id1.w & ~63) + (c0 + 7), v1.w);
    }
}

extern "C" void kernel_launch(void* const* d_in, const int* in_sizes, int n_in,
                              void* d_out, int out_size)
{
    const float* in  = (const float*)d_in[0];
    const int*   idx = (const int*)d_in[1];
    float*       out = (float*)d_out;

    cudaLaunchAttribute attrs[1];
    attrs[0].id = cudaLaunchAttributeProgrammaticStreamSerialization;
    attrs[0].val.programmaticStreamSerializationAllowed = 1;

    cudaLaunchConfig_t cfg = {};
    cfg.gridDim  = dim3(GRID, 1, 1);
    cfg.blockDim = dim3(BLOCK, 1, 1);
    cfg.stream   = 0;

    // Prologue: zero slab 0 only.
    cfg.attrs = nullptr;  cfg.numAttrs = 0;
    cudaLaunchKernelEx(&cfg, unpool_pdl2_kernel, in, idx, out, -1, 0);

    // Pipelined chain: dependent may start as soon as predecessor has zeroed
    // its slab and fired launch_dependents.
    cfg.attrs = attrs;  cfg.numAttrs = 1;
    for (int b = 0; b < 8; b++)
        cudaLaunchKernelEx(&cfg, unpool_pdl2_kernel, in, idx, out,
                           b, b < 7 ? b + 1 : -1);
}